// round 7
// baseline (speedup 1.0000x reference)
#include <cuda_runtime.h>
#include <cuda_bf16.h>
#include <cuda_fp16.h>
#include <cstdint>

#define N_NODES_MAX 50048
#define E_MAX 1600000
#define DIM 128
#define BN_EPS 1e-5f

// ---------------- device scratch ----------------
__device__ __half g_h[N_NODES_MAX * DIM];     // x @ W in fp16 (gather payload)
__device__ float g_agg[N_NODES_MAX * DIM];
__device__ float g_dinv[N_NODES_MAX];
__device__ int   g_cnt[N_NODES_MAX];
__device__ int   g_row[N_NODES_MAX];          // local scan start; after fill -> local end
__device__ int   g_part[64];                  // cross-block scan offsets
__device__ int   g_esrc[E_MAX];
__device__ float g_stats[2 * DIM];

// ---------------- stream/event fork-join resources (static init) ------
struct ForkRes {
    cudaStream_t s;
    cudaEvent_t e0, e1;
    ForkRes() {
        cudaStreamCreateWithFlags(&s, cudaStreamNonBlocking);
        cudaEventCreateWithFlags(&e0, cudaEventDisableTiming);
        cudaEventCreateWithFlags(&e1, cudaEventDisableTiming);
    }
};
static ForkRes g_fork;

// ---------------- init ----------------
__global__ void init_kernel(int n) {
    int i = blockIdx.x * blockDim.x + threadIdx.x;
    if (i < n) g_cnt[i] = 0;
    if (i < 2 * DIM) g_stats[i] = 0.0f;
}

// degree: 4 edges per thread via int4
__global__ void deg_kernel(const int* __restrict__ dst, int E4) {
    int e = blockIdx.x * blockDim.x + threadIdx.x;
    if (e < E4) {
        int4 d = __ldg((const int4*)dst + e);
        atomicAdd(&g_cnt[d.x], 1);
        atomicAdd(&g_cnt[d.y], 1);
        atomicAdd(&g_cnt[d.z], 1);
        atomicAdd(&g_cnt[d.w], 1);
    }
}

// ---------------- exclusive scan (+ dinv fused) ----------------
__global__ __launch_bounds__(1024) void scan1_kernel(int n) {
    __shared__ int wsum[32];
    int i = blockIdx.x * 1024 + threadIdx.x;
    int lane = threadIdx.x & 31, wid = threadIdx.x >> 5;
    int v = (i < n) ? g_cnt[i] : 0;
    if (i < n) g_dinv[i] = rsqrtf((float)(v + 1));
    int s = v;
#pragma unroll
    for (int o = 1; o < 32; o <<= 1) {
        int t = __shfl_up_sync(0xffffffffu, s, o);
        if (lane >= o) s += t;
    }
    if (lane == 31) wsum[wid] = s;
    __syncthreads();
    if (wid == 0) {
        int ws = wsum[lane];
#pragma unroll
        for (int o = 1; o < 32; o <<= 1) {
            int t = __shfl_up_sync(0xffffffffu, ws, o);
            if (lane >= o) ws += t;
        }
        wsum[lane] = ws;
    }
    __syncthreads();
    int base = (wid > 0) ? wsum[wid - 1] : 0;
    if (i < n) g_row[i] = s - v + base;          // block-local exclusive start
    if (threadIdx.x == 1023) g_part[blockIdx.x] = s + base;
}

__global__ void scan2_kernel(int nb) {
    int lane = threadIdx.x;
    int i0 = 2 * lane, i1 = 2 * lane + 1;
    int v0 = (i0 < nb) ? g_part[i0] : 0;
    int v1 = (i1 < nb) ? g_part[i1] : 0;
    int p = v0 + v1;
    int s = p;
#pragma unroll
    for (int o = 1; o < 32; o <<= 1) {
        int t = __shfl_up_sync(0xffffffffu, s, o);
        if (lane >= o) s += t;
    }
    int ex = s - p;
    if (i0 < nb) g_part[i0] = ex;
    if (i1 < nb) g_part[i1] = ex + v0;
}

// fill: local cursor in g_row, cross-block offset added here (scan3 folded in)
__global__ void fill_kernel(const int* __restrict__ src,
                            const int* __restrict__ dst, int E4) {
    int e = blockIdx.x * blockDim.x + threadIdx.x;
    if (e >= E4) return;
    int4 d = __ldg((const int4*)dst + e);
    int4 sv = __ldg((const int4*)src + e);
    int p0 = atomicAdd(&g_row[d.x], 1) + __ldg(&g_part[d.x >> 10]);
    g_esrc[p0] = sv.x;
    int p1 = atomicAdd(&g_row[d.y], 1) + __ldg(&g_part[d.y >> 10]);
    g_esrc[p1] = sv.y;
    int p2 = atomicAdd(&g_row[d.z], 1) + __ldg(&g_part[d.z >> 10]);
    g_esrc[p2] = sv.z;
    int p3 = atomicAdd(&g_row[d.w], 1) + __ldg(&g_part[d.w >> 10]);
    g_esrc[p3] = sv.w;
}

// ---------------- fp16 hi/lo tensor-core GEMM: h = x @ W --------------
// Split at staging: x = hi + lo (fp16 each); h = hi*hi + hi*lo + lo*hi (fp32 acc).
// Block 128x128, 8 warps (rowg=wid&3 -> 32 rows, colg=wid>>2 -> 64 cols), KC=32.
__device__ __forceinline__ void mma_f16(float* c, uint32_t a0, uint32_t a1,
                                        uint32_t a2, uint32_t a3,
                                        uint32_t b0, uint32_t b1) {
    asm volatile(
        "mma.sync.aligned.m16n8k16.row.col.f32.f16.f16.f32 "
        "{%0,%1,%2,%3}, {%4,%5,%6,%7}, {%8,%9}, {%0,%1,%2,%3};"
        : "+f"(c[0]), "+f"(c[1]), "+f"(c[2]), "+f"(c[3])
        : "r"(a0), "r"(a1), "r"(a2), "r"(a3), "r"(b0), "r"(b1));
}

#define KC 32
#define XPAD 40   // row stride in halves (80B): conflict-free for frag loads
__global__ __launch_bounds__(256) void gemm_tc_kernel(
    const float* __restrict__ x, const float* __restrict__ W, int n)
{
    __shared__ __half xs_hi[128][XPAD];
    __shared__ __half xs_lo[128][XPAD];
    __shared__ __half wt_hi[128][XPAD];   // transposed: [n][k]
    __shared__ __half wt_lo[128][XPAD];

    const int t = threadIdx.x;
    const int wid = t >> 5, lane = t & 31;
    const int rowg = wid & 3, colg = wid >> 2;
    const int g = lane >> 2, t4 = lane & 3;
    const int row0 = blockIdx.x * 128;

    float acc[2][8][4];
#pragma unroll
    for (int mi = 0; mi < 2; mi++)
#pragma unroll
        for (int nt = 0; nt < 8; nt++)
#pragma unroll
            for (int c = 0; c < 4; c++) acc[mi][nt][c] = 0.f;

    for (int kc = 0; kc < DIM; kc += KC) {
        // stage x chunk: 128 rows x 32 k, split hi/lo
        for (int idx = t; idx < 1024; idx += 256) {
            int r = idx >> 3, k4 = (idx & 7) << 2;
            int row = row0 + r;
            float4 v = make_float4(0.f, 0.f, 0.f, 0.f);
            if (row < n) v = *(const float4*)(x + (size_t)row * DIM + kc + k4);
            float vv[4] = {v.x, v.y, v.z, v.w};
            __half h[4], l[4];
#pragma unroll
            for (int j = 0; j < 4; j++) {
                h[j] = __float2half(vv[j]);
                l[j] = __float2half(vv[j] - __half2float(h[j]));
            }
            __half2 h01; h01.x = h[0]; h01.y = h[1];
            __half2 h23; h23.x = h[2]; h23.y = h[3];
            __half2 l01; l01.x = l[0]; l01.y = l[1];
            __half2 l23; l23.x = l[2]; l23.y = l[3];
            *(__half2*)&xs_hi[r][k4]     = h01;
            *(__half2*)&xs_hi[r][k4 + 2] = h23;
            *(__half2*)&xs_lo[r][k4]     = l01;
            *(__half2*)&xs_lo[r][k4 + 2] = l23;
        }
        // stage W chunk transposed: wt[n][k] = W[kc+k][n], split hi/lo
        for (int idx = t; idx < 1024; idx += 256) {
            int k = idx >> 5, n4 = (idx & 31) << 2;
            float4 v = *(const float4*)(W + (size_t)(kc + k) * DIM + n4);
            float vv[4] = {v.x, v.y, v.z, v.w};
#pragma unroll
            for (int j = 0; j < 4; j++) {
                __half hh = __float2half(vv[j]);
                __half ll = __float2half(vv[j] - __half2float(hh));
                wt_hi[n4 + j][k] = hh;
                wt_lo[n4 + j][k] = ll;
            }
        }
        __syncthreads();

#pragma unroll
        for (int ks = 0; ks < KC; ks += 16) {
            uint32_t ahi[2][4], alo[2][4];
#pragma unroll
            for (int mi = 0; mi < 2; mi++) {
                int rb = rowg * 32 + mi * 16;
                int k0 = ks + 2 * t4;
                ahi[mi][0] = *(uint32_t*)&xs_hi[rb + g][k0];
                ahi[mi][1] = *(uint32_t*)&xs_hi[rb + g + 8][k0];
                ahi[mi][2] = *(uint32_t*)&xs_hi[rb + g][k0 + 8];
                ahi[mi][3] = *(uint32_t*)&xs_hi[rb + g + 8][k0 + 8];
                alo[mi][0] = *(uint32_t*)&xs_lo[rb + g][k0];
                alo[mi][1] = *(uint32_t*)&xs_lo[rb + g + 8][k0];
                alo[mi][2] = *(uint32_t*)&xs_lo[rb + g][k0 + 8];
                alo[mi][3] = *(uint32_t*)&xs_lo[rb + g + 8][k0 + 8];
            }
#pragma unroll
            for (int nt = 0; nt < 8; nt++) {
                int col = colg * 64 + nt * 8 + g;
                int k0 = ks + 2 * t4;
                uint32_t bh0 = *(uint32_t*)&wt_hi[col][k0];
                uint32_t bh1 = *(uint32_t*)&wt_hi[col][k0 + 8];
                uint32_t bl0 = *(uint32_t*)&wt_lo[col][k0];
                uint32_t bl1 = *(uint32_t*)&wt_lo[col][k0 + 8];
#pragma unroll
                for (int mi = 0; mi < 2; mi++) {
                    mma_f16(acc[mi][nt], ahi[mi][0], ahi[mi][1], ahi[mi][2], ahi[mi][3], bh0, bh1);
                    mma_f16(acc[mi][nt], ahi[mi][0], ahi[mi][1], ahi[mi][2], ahi[mi][3], bl0, bl1);
                    mma_f16(acc[mi][nt], alo[mi][0], alo[mi][1], alo[mi][2], alo[mi][3], bh0, bh1);
                }
            }
        }
        __syncthreads();
    }

#pragma unroll
    for (int mi = 0; mi < 2; mi++) {
        int rb = row0 + rowg * 32 + mi * 16;
#pragma unroll
        for (int nt = 0; nt < 8; nt++) {
            int col = colg * 64 + nt * 8 + 2 * t4;
            int r0 = rb + g, r1 = rb + g + 8;
            if (r0 < n)
                *(__half2*)(g_h + (size_t)r0 * DIM + col) =
                    __floats2half2_rn(acc[mi][nt][0], acc[mi][nt][1]);
            if (r1 < n)
                *(__half2*)(g_h + (size_t)r1 * DIM + col) =
                    __floats2half2_rn(acc[mi][nt][2], acc[mi][nt][3]);
        }
    }
}

// ---------------- per-node accumulate + fused BN stats ----------------
__device__ __forceinline__ void fma_row(float4& acc, uint2 raw, float nm) {
    __half2 p0 = *(__half2*)&raw.x, p1 = *(__half2*)&raw.y;
    float2 f0 = __half22float2(p0), f1 = __half22float2(p1);
    acc.x += f0.x * nm; acc.y += f0.y * nm;
    acc.z += f1.x * nm; acc.w += f1.y * nm;
}

__global__ __launch_bounds__(256) void acc_kernel(const float* __restrict__ b, int n)
{
    __shared__ float ssum[8][128];
    __shared__ float ssq[8][128];
    const int w = (blockIdx.x * blockDim.x + threadIdx.x) >> 5;
    const int wid = threadIdx.x >> 5;
    const int lane = threadIdx.x & 31;

    float4 acc = make_float4(0.f, 0.f, 0.f, 0.f);
    if (w < n) {
        float di = g_dinv[w];
        acc = __ldg((const float4*)b + lane);
        {
            uint2 raw = __ldg((const uint2*)(g_h + (size_t)w * DIM) + lane);
            fma_row(acc, raw, di * di);
        }
        const int cnt = g_cnt[w];
        const int beg = g_row[w] + __ldg(&g_part[w >> 10]) - cnt;  // local end + offset - cnt
        int j = 0;
        for (; j + 8 <= cnt; j += 8) {
            int s[8];
            float nm[8];
            uint2 r[8];
#pragma unroll
            for (int q = 0; q < 8; q++) s[q] = __ldg(g_esrc + beg + j + q);
#pragma unroll
            for (int q = 0; q < 8; q++) nm[q] = di * __ldg(g_dinv + s[q]);
#pragma unroll
            for (int q = 0; q < 8; q++)
                r[q] = __ldg((const uint2*)(g_h + (size_t)s[q] * DIM) + lane);
#pragma unroll
            for (int q = 0; q < 8; q++) fma_row(acc, r[q], nm[q]);
        }
        for (; j < cnt; j++) {
            int s0 = __ldg(g_esrc + beg + j);
            float nm0 = di * __ldg(g_dinv + s0);
            uint2 r0 = __ldg((const uint2*)(g_h + (size_t)s0 * DIM) + lane);
            fma_row(acc, r0, nm0);
        }
        *((float4*)(g_agg + (size_t)w * DIM) + lane) = acc;
    }
    *(float4*)&ssum[wid][lane * 4] = acc;
    float4 sq = make_float4(acc.x * acc.x, acc.y * acc.y, acc.z * acc.z, acc.w * acc.w);
    *(float4*)&ssq[wid][lane * 4] = sq;
    __syncthreads();

    int t = threadIdx.x;
    if (t < 128) {
        float s = 0.f;
#pragma unroll
        for (int k = 0; k < 8; k++) s += ssum[k][t];
        atomicAdd(&g_stats[t], s);
    } else {
        int d = t - 128;
        float s = 0.f;
#pragma unroll
        for (int k = 0; k < 8; k++) s += ssq[k][d];
        atomicAdd(&g_stats[DIM + d], s);
    }
}

// ---------------- epilogue: finalize fused, relu(BN(agg)) + x ---------
__global__ __launch_bounds__(256) void out_kernel(
    const float* __restrict__ x, const float* __restrict__ gamma,
    const float* __restrict__ beta, float* __restrict__ out,
    float inv_n, int total4)
{
    __shared__ float ssc[DIM];
    __shared__ float ssh[DIM];
    int t = threadIdx.x;
    if (t < DIM) {
        float mean = g_stats[t] * inv_n;
        float var  = g_stats[DIM + t] * inv_n - mean * mean;
        float sc = gamma[t] * rsqrtf(var + BN_EPS);
        ssc[t] = sc;
        ssh[t] = beta[t] - mean * sc;
    }
    __syncthreads();

    int i = blockIdx.x * blockDim.x + t;
    if (i >= total4) return;
    int d4 = i & 31;
    float4 a  = ((const float4*)g_agg)[i];
    float4 sc = *(float4*)&ssc[d4 * 4];
    float4 sh = *(float4*)&ssh[d4 * 4];
    float4 xv = ((const float4*)x)[i];
    float4 y;
    y.x = fmaxf(a.x * sc.x + sh.x, 0.f) + xv.x;
    y.y = fmaxf(a.y * sc.y + sh.y, 0.f) + xv.y;
    y.z = fmaxf(a.z * sc.z + sh.z, 0.f) + xv.z;
    y.w = fmaxf(a.w * sc.w + sh.w, 0.f) + xv.w;
    ((float4*)out)[i] = y;
}

// ---------------- launch ----------------------------------------------
extern "C" void kernel_launch(void* const* d_in, const int* in_sizes, int n_in,
                              void* d_out, int out_size)
{
    const float* x     = (const float*)d_in[0];
    const float* W     = (const float*)d_in[1];
    const float* b     = (const float*)d_in[2];
    const float* gamma = (const float*)d_in[3];
    const float* beta  = (const float*)d_in[4];
    const int*   ei    = (const int*)d_in[5];

    const int n = in_sizes[0] / DIM;
    const int E = in_sizes[5] / 2;
    const int* src = ei;
    const int* dst = ei + E;
    const int E4 = E / 4;           // E = 1.6M, divisible by 4

    // fork: GEMM on side stream, overlapping the CSR build chain
    cudaEventRecord(g_fork.e0, 0);
    cudaStreamWaitEvent(g_fork.s, g_fork.e0, 0);
    gemm_tc_kernel<<<(n + 127) / 128, 256, 0, g_fork.s>>>(x, W, n);
    cudaEventRecord(g_fork.e1, g_fork.s);

    // main chain: CSR build
    init_kernel<<<(n + 255) / 256, 256>>>(n);
    deg_kernel<<<(E4 + 255) / 256, 256>>>(dst, E4);
    int nb = (n + 1023) / 1024;
    scan1_kernel<<<nb, 1024>>>(n);          // also writes dinv
    scan2_kernel<<<1, 32>>>(nb);
    fill_kernel<<<(E4 + 255) / 256, 256>>>(src, dst, E4);

    // join: acc needs both g_h (side) and CSR (main)
    cudaStreamWaitEvent(0, g_fork.e1, 0);
    acc_kernel<<<(n + 7) / 8, 256>>>(b, n);

    int total4 = n * DIM / 4;
    out_kernel<<<(total4 + 255) / 256, 256>>>(x, gamma, beta, (float*)d_out,
                                              1.0f / (float)n, total4);
}

// round 8
// speedup vs baseline: 1.0449x; 1.0449x over previous
#include <cuda_runtime.h>
#include <cuda_bf16.h>
#include <cuda_fp16.h>
#include <cstdint>

#define N_NODES_MAX 50048
#define E_MAX 1600000
#define DIM 128
#define BN_EPS 1e-5f

// ---------------- device scratch ----------------
__device__ __half g_h[N_NODES_MAX * DIM];     // x @ W in fp16 (gather payload)
__device__ float g_agg[N_NODES_MAX * DIM];
__device__ float g_dinv[N_NODES_MAX];
__device__ int   g_cnt[N_NODES_MAX];
__device__ int   g_row[N_NODES_MAX];          // scan -> start; after fill -> end
__device__ int   g_part[64];                  // raw block partials from scan1
__device__ int   g_esrc[E_MAX];
__device__ float g_stats[2 * DIM];

// ---------------- stream/event fork-join resources (static init) ------
struct ForkRes {
    cudaStream_t s;
    cudaEvent_t e0, e1;
    ForkRes() {
        cudaStreamCreateWithFlags(&s, cudaStreamNonBlocking);
        cudaEventCreateWithFlags(&e0, cudaEventDisableTiming);
        cudaEventCreateWithFlags(&e1, cudaEventDisableTiming);
    }
};
static ForkRes g_fork;

// ---------------- init ----------------
__global__ void init_kernel(int n) {
    int i = blockIdx.x * blockDim.x + threadIdx.x;
    if (i < n) g_cnt[i] = 0;
    if (i < 2 * DIM) g_stats[i] = 0.0f;
}

__global__ void deg_kernel(const int* __restrict__ dst, int E) {
    int e = blockIdx.x * blockDim.x + threadIdx.x;
    if (e < E) atomicAdd(&g_cnt[dst[e]], 1);
}

// ---------------- exclusive scan (+ dinv fused) ----------------
__global__ __launch_bounds__(1024) void scan1_kernel(int n) {
    __shared__ int wsum[32];
    int i = blockIdx.x * 1024 + threadIdx.x;
    int lane = threadIdx.x & 31, wid = threadIdx.x >> 5;
    int v = (i < n) ? g_cnt[i] : 0;
    if (i < n) g_dinv[i] = rsqrtf((float)(v + 1));
    int s = v;
#pragma unroll
    for (int o = 1; o < 32; o <<= 1) {
        int t = __shfl_up_sync(0xffffffffu, s, o);
        if (lane >= o) s += t;
    }
    if (lane == 31) wsum[wid] = s;
    __syncthreads();
    if (wid == 0) {
        int ws = wsum[lane];
#pragma unroll
        for (int o = 1; o < 32; o <<= 1) {
            int t = __shfl_up_sync(0xffffffffu, ws, o);
            if (lane >= o) ws += t;
        }
        wsum[lane] = ws;
    }
    __syncthreads();
    int base = (wid > 0) ? wsum[wid - 1] : 0;
    if (i < n) g_row[i] = s - v + base;          // block-local exclusive start
    if (threadIdx.x == 1023) g_part[blockIdx.x] = s + base;
}

// scan3: each block warp-scans the raw partials itself (nb <= 64) — no scan2 launch
__global__ __launch_bounds__(1024) void scan3_kernel(int n, int nb) {
    __shared__ int off;
    if (threadIdx.x < 32) {
        int lane = threadIdx.x;
        int i0 = 2 * lane, i1 = 2 * lane + 1;
        int v0 = (i0 < nb) ? g_part[i0] : 0;
        int v1 = (i1 < nb) ? g_part[i1] : 0;
        int p = v0 + v1;
        int s = p;
#pragma unroll
        for (int o = 1; o < 32; o <<= 1) {
            int t = __shfl_up_sync(0xffffffffu, s, o);
            if (lane >= o) s += t;
        }
        int ex = s - p;                     // pairs strictly before this lane
        int b = blockIdx.x;
        if ((b >> 1) == lane) off = ex + ((b & 1) ? v0 : 0);
    }
    __syncthreads();
    int i = blockIdx.x * 1024 + threadIdx.x;
    if (i < n) g_row[i] += off;
}

// fill: cursor fused into g_row (becomes end offset)
__global__ void fill_kernel(const int* __restrict__ src,
                            const int* __restrict__ dst, int E) {
    int e = blockIdx.x * blockDim.x + threadIdx.x;
    if (e < E) {
        int d = dst[e];
        int pos = atomicAdd(&g_row[d], 1);
        g_esrc[pos] = src[e];
    }
}

// ---------------- 3xTF32 tensor-core GEMM: h = x @ W (fp16 out) -------
__device__ __forceinline__ void split_tf32(float v, uint32_t& hi, uint32_t& lo) {
    uint32_t h;
    asm("cvt.rna.tf32.f32 %0, %1;" : "=r"(h) : "f"(v));
    float lf = v - __uint_as_float(h);
    asm("cvt.rna.tf32.f32 %0, %1;" : "=r"(lo) : "f"(lf));
    hi = h;
}

__device__ __forceinline__ void mma_tf32(float* c, uint32_t a0, uint32_t a1,
                                         uint32_t a2, uint32_t a3,
                                         uint32_t b0, uint32_t b1) {
    asm volatile(
        "mma.sync.aligned.m16n8k8.row.col.f32.tf32.tf32.f32 "
        "{%0,%1,%2,%3}, {%4,%5,%6,%7}, {%8,%9}, {%0,%1,%2,%3};"
        : "+f"(c[0]), "+f"(c[1]), "+f"(c[2]), "+f"(c[3])
        : "r"(a0), "r"(a1), "r"(a2), "r"(a3), "r"(b0), "r"(b1));
}

#define KC 32
__global__ __launch_bounds__(256, 2) void gemm_tc_kernel(
    const float* __restrict__ x, const float* __restrict__ W, int n)
{
    __shared__ float xs[128][36];
    __shared__ float ws[KC][132];

    const int t = threadIdx.x;
    const int wid = t >> 5, lane = t & 31;
    const int rowg = wid & 3, colg = wid >> 2;
    const int g = lane >> 2, t4 = lane & 3;
    const int row0 = blockIdx.x * 128;

    float acc[2][8][4];
#pragma unroll
    for (int mi = 0; mi < 2; mi++)
#pragma unroll
        for (int nt = 0; nt < 8; nt++)
#pragma unroll
            for (int c = 0; c < 4; c++) acc[mi][nt][c] = 0.f;

    for (int kc = 0; kc < DIM; kc += KC) {
        for (int idx = t; idx < 1024; idx += 256) {
            int r = idx >> 3, k4 = (idx & 7) << 2;
            int row = row0 + r;
            float4 v = make_float4(0.f, 0.f, 0.f, 0.f);
            if (row < n) v = *(const float4*)(x + (size_t)row * DIM + kc + k4);
            *(float4*)&xs[r][k4] = v;
        }
        for (int idx = t; idx < 1024; idx += 256) {
            int k = idx >> 5, n4 = (idx & 31) << 2;
            *(float4*)&ws[k][n4] = *(const float4*)(W + (size_t)(kc + k) * DIM + n4);
        }
        __syncthreads();

#pragma unroll
        for (int ks = 0; ks < KC; ks += 8) {
            uint32_t ahi[2][4], alo[2][4];
#pragma unroll
            for (int mi = 0; mi < 2; mi++) {
                int rb = rowg * 32 + mi * 16;
                split_tf32(xs[rb + g][ks + t4],          ahi[mi][0], alo[mi][0]);
                split_tf32(xs[rb + g + 8][ks + t4],      ahi[mi][1], alo[mi][1]);
                split_tf32(xs[rb + g][ks + t4 + 4],      ahi[mi][2], alo[mi][2]);
                split_tf32(xs[rb + g + 8][ks + t4 + 4],  ahi[mi][3], alo[mi][3]);
            }
#pragma unroll
            for (int nt = 0; nt < 8; nt++) {
                int cb = colg * 64 + nt * 8;
                uint32_t bhi0, blo0, bhi1, blo1;
                split_tf32(ws[ks + t4][cb + g],     bhi0, blo0);
                split_tf32(ws[ks + t4 + 4][cb + g], bhi1, blo1);
#pragma unroll
                for (int mi = 0; mi < 2; mi++) {
                    mma_tf32(acc[mi][nt], ahi[mi][0], ahi[mi][1], ahi[mi][2], ahi[mi][3], bhi0, bhi1);
                    mma_tf32(acc[mi][nt], ahi[mi][0], ahi[mi][1], ahi[mi][2], ahi[mi][3], blo0, blo1);
                    mma_tf32(acc[mi][nt], alo[mi][0], alo[mi][1], alo[mi][2], alo[mi][3], bhi0, bhi1);
                }
            }
        }
        __syncthreads();
    }

#pragma unroll
    for (int mi = 0; mi < 2; mi++) {
        int rb = row0 + rowg * 32 + mi * 16;
#pragma unroll
        for (int nt = 0; nt < 8; nt++) {
            int col = colg * 64 + nt * 8 + 2 * t4;
            int r0 = rb + g, r1 = rb + g + 8;
            if (r0 < n)
                *(__half2*)(g_h + (size_t)r0 * DIM + col) =
                    __floats2half2_rn(acc[mi][nt][0], acc[mi][nt][1]);
            if (r1 < n)
                *(__half2*)(g_h + (size_t)r1 * DIM + col) =
                    __floats2half2_rn(acc[mi][nt][2], acc[mi][nt][3]);
        }
    }
}

// ---------------- per-node accumulate + fused BN stats ----------------
__device__ __forceinline__ void fma_row(float4& acc, uint2 raw, float nm) {
    __half2 p0 = *(__half2*)&raw.x, p1 = *(__half2*)&raw.y;
    float2 f0 = __half22float2(p0), f1 = __half22float2(p1);
    acc.x += f0.x * nm; acc.y += f0.y * nm;
    acc.z += f1.x * nm; acc.w += f1.y * nm;
}

__global__ __launch_bounds__(256) void acc_kernel(const float* __restrict__ b, int n)
{
    __shared__ float ssum[8][128];
    __shared__ float ssq[8][128];
    const int w = (blockIdx.x * blockDim.x + threadIdx.x) >> 5;
    const int wid = threadIdx.x >> 5;
    const int lane = threadIdx.x & 31;

    float4 acc = make_float4(0.f, 0.f, 0.f, 0.f);
    if (w < n) {
        float di = g_dinv[w];
        acc = __ldg((const float4*)b + lane);
        // self loop (norm = dinv^2)
        {
            uint2 raw = __ldg((const uint2*)(g_h + (size_t)w * DIM) + lane);
            fma_row(acc, raw, di * di);
        }
        const int end = g_row[w];       // post-fill end offset
        const int cnt = g_cnt[w];
        const int beg = end - cnt;
        int j = 0;
        for (; j + 4 <= cnt; j += 4) {
            int s0 = __ldg(g_esrc + beg + j);
            int s1 = __ldg(g_esrc + beg + j + 1);
            int s2 = __ldg(g_esrc + beg + j + 2);
            int s3 = __ldg(g_esrc + beg + j + 3);
            float nm0 = di * __ldg(g_dinv + s0);
            float nm1 = di * __ldg(g_dinv + s1);
            float nm2 = di * __ldg(g_dinv + s2);
            float nm3 = di * __ldg(g_dinv + s3);
            uint2 r0 = __ldg((const uint2*)(g_h + (size_t)s0 * DIM) + lane);
            uint2 r1 = __ldg((const uint2*)(g_h + (size_t)s1 * DIM) + lane);
            uint2 r2 = __ldg((const uint2*)(g_h + (size_t)s2 * DIM) + lane);
            uint2 r3 = __ldg((const uint2*)(g_h + (size_t)s3 * DIM) + lane);
            fma_row(acc, r0, nm0);
            fma_row(acc, r1, nm1);
            fma_row(acc, r2, nm2);
            fma_row(acc, r3, nm3);
        }
        for (; j < cnt; j++) {
            int s0 = __ldg(g_esrc + beg + j);
            float nm0 = di * __ldg(g_dinv + s0);
            uint2 r0 = __ldg((const uint2*)(g_h + (size_t)s0 * DIM) + lane);
            fma_row(acc, r0, nm0);
        }
        *((float4*)(g_agg + (size_t)w * DIM) + lane) = acc;
    }
    *(float4*)&ssum[wid][lane * 4] = acc;
    float4 sq = make_float4(acc.x * acc.x, acc.y * acc.y, acc.z * acc.z, acc.w * acc.w);
    *(float4*)&ssq[wid][lane * 4] = sq;
    __syncthreads();

    int t = threadIdx.x;
    if (t < 128) {
        float s = 0.f;
#pragma unroll
        for (int k = 0; k < 8; k++) s += ssum[k][t];
        atomicAdd(&g_stats[t], s);
    } else {
        int d = t - 128;
        float s = 0.f;
#pragma unroll
        for (int k = 0; k < 8; k++) s += ssq[k][d];
        atomicAdd(&g_stats[DIM + d], s);
    }
}

// ---------------- epilogue: finalize fused, relu(BN(agg)) + x ---------
__global__ __launch_bounds__(256) void out_kernel(
    const float* __restrict__ x, const float* __restrict__ gamma,
    const float* __restrict__ beta, float* __restrict__ out,
    float inv_n, int total4)
{
    __shared__ float ssc[DIM];
    __shared__ float ssh[DIM];
    int t = threadIdx.x;
    if (t < DIM) {
        float mean = g_stats[t] * inv_n;
        float var  = g_stats[DIM + t] * inv_n - mean * mean;
        float sc = gamma[t] * rsqrtf(var + BN_EPS);
        ssc[t] = sc;
        ssh[t] = beta[t] - mean * sc;
    }
    __syncthreads();

    int i = blockIdx.x * blockDim.x + t;
    if (i >= total4) return;
    int d4 = i & 31;
    float4 a  = ((const float4*)g_agg)[i];
    float4 sc = *(float4*)&ssc[d4 * 4];
    float4 sh = *(float4*)&ssh[d4 * 4];
    float4 xv = ((const float4*)x)[i];
    float4 y;
    y.x = fmaxf(a.x * sc.x + sh.x, 0.f) + xv.x;
    y.y = fmaxf(a.y * sc.y + sh.y, 0.f) + xv.y;
    y.z = fmaxf(a.z * sc.z + sh.z, 0.f) + xv.z;
    y.w = fmaxf(a.w * sc.w + sh.w, 0.f) + xv.w;
    ((float4*)out)[i] = y;
}

// ---------------- launch ----------------------------------------------
extern "C" void kernel_launch(void* const* d_in, const int* in_sizes, int n_in,
                              void* d_out, int out_size)
{
    const float* x     = (const float*)d_in[0];
    const float* W     = (const float*)d_in[1];
    const float* b     = (const float*)d_in[2];
    const float* gamma = (const float*)d_in[3];
    const float* beta  = (const float*)d_in[4];
    const int*   ei    = (const int*)d_in[5];

    const int n = in_sizes[0] / DIM;
    const int E = in_sizes[5] / 2;
    const int* src = ei;
    const int* dst = ei + E;

    // fork: GEMM on side stream, overlapping the CSR build chain
    cudaEventRecord(g_fork.e0, 0);
    cudaStreamWaitEvent(g_fork.s, g_fork.e0, 0);
    gemm_tc_kernel<<<(n + 127) / 128, 256, 0, g_fork.s>>>(x, W, n);
    cudaEventRecord(g_fork.e1, g_fork.s);

    // main chain: CSR build
    init_kernel<<<(n + 255) / 256, 256>>>(n);
    deg_kernel<<<(E + 255) / 256, 256>>>(dst, E);
    int nb = (n + 1023) / 1024;
    scan1_kernel<<<nb, 1024>>>(n);          // also writes dinv
    scan3_kernel<<<nb, 1024>>>(n, nb);      // self-scans partials (no scan2)
    fill_kernel<<<(E + 255) / 256, 256>>>(src, dst, E);

    // join: acc needs both g_h (side) and CSR (main)
    cudaStreamWaitEvent(0, g_fork.e1, 0);
    acc_kernel<<<(n + 7) / 8, 256>>>(b, n);

    int total4 = n * DIM / 4;
    out_kernel<<<(total4 + 255) / 256, 256>>>(x, gamma, beta, (float*)d_out,
                                              1.0f / (float)n, total4);
}